// round 14
// baseline (speedup 1.0000x reference)
#include <cuda_runtime.h>
#include <cuda_fp16.h>
#include <math.h>

#define Dd 768
#define Pp 576
#define Gg 24
#define Kk 8
#define FPn 64
#define Ac 16
#define Bb 32
#define NEGC -1000000000.0f
#define TEMPc 0.1f
#define ROWS (Bb*Pp)            /* 18432 */
#define SLICE ((long)ROWS*Dd)

#define NIT 24                  /* 768 / 32 */
#define H_STG 24576             /* A 16KB + B 8KB per stage */
#define H_SMEM (2*H_STG)

#define MODW_BLOCKS ((3*Dd*Dd)/64)   /* 27648 */

typedef unsigned long long ull;

// ------------------------- scratch (device globals) ------------------------
__device__ float g_Wcomb[2*Dd*Dd];      // fp32 combined weights: q | k
__device__ float g_WvT[Dd*Dd];          // Wv_eff transposed: [d][j]
__device__ float g_bias[3*Dd];
__device__ float g_be[Dd];              // Wo @ bv + bo
__device__ float g_qkv[2*ROWS*Dd];      // q | k (fp32)
__device__ float g_scores[Bb*Pp*Pp];
__device__ float g_cnorm[Pp];
__device__ float g_anchors_n[Ac*Dd];
__device__ float g_fpbias[Ac];
__device__ float g_pooled[Bb*Dd];
__device__ float g_wpool[Bb*Ac*Dd];
__device__ float g_anchor_out[Bb*Dd];

// fp16 split buffers (output-only path)
__device__ __half g_Wc2hi[Dd*Dd];       // (Wo @ Wv_eff) hi
__device__ __half g_Wc2lo[Dd*Dd];
__device__ __half g_Rhi[ROWS*Dd];       // gathered-x hi
__device__ __half g_Rlo[ROWS*Dd];

#define LO_SCALE 2048.0f
#define LO_INV   (1.0f/2048.0f)

// ------------------------- f32x2 helpers ------------------------------------
__device__ __forceinline__ void ffma2(ull &acc, ull a, ull b) {
    asm("fma.rn.f32x2 %0, %1, %2, %0;" : "+l"(acc) : "l"(a), "l"(b));
}
__device__ __forceinline__ ull pack2(float x, float y) {
    ull r;
    asm("mov.b64 %0, {%1, %2};" : "=l"(r) : "f"(x), "f"(y));
    return r;
}
__device__ __forceinline__ float2 unpack2(ull v) {
    float2 r;
    asm("mov.b64 {%0, %1}, %2;" : "=f"(r.x), "=f"(r.y) : "l"(v));
    return r;
}

// ------------------------- PTX helpers (HMMA path) ---------------------------
__device__ __forceinline__ unsigned smem_u32(const void* p) {
    unsigned a;
    asm("{ .reg .u64 t; cvta.to.shared.u64 t, %1; cvt.u32.u64 %0, t; }" : "=r"(a) : "l"(p));
    return a;
}
__device__ __forceinline__ void cp16(unsigned s, const void* g) {
    asm volatile("cp.async.ca.shared.global [%0], [%1], 16;" :: "r"(s), "l"(g) : "memory");
}
__device__ __forceinline__ void cp_commit() {
    asm volatile("cp.async.commit_group;" ::: "memory");
}
template<int N> __device__ __forceinline__ void cp_wait() {
    asm volatile("cp.async.wait_group %0;" :: "n"(N) : "memory");
}
__device__ __forceinline__ void ldsm4(unsigned* r, unsigned addr) {
    asm volatile("ldmatrix.sync.aligned.m8n8.x4.shared.b16 {%0,%1,%2,%3}, [%4];"
        : "=r"(r[0]), "=r"(r[1]), "=r"(r[2]), "=r"(r[3]) : "r"(addr));
}
__device__ __forceinline__ void mma16816(float* d, const unsigned* a, const unsigned* b) {
    asm volatile(
        "mma.sync.aligned.m16n8k16.row.col.f32.f16.f16.f32 "
        "{%0,%1,%2,%3}, {%4,%5,%6,%7}, {%8,%9}, {%0,%1,%2,%3};"
        : "+f"(d[0]), "+f"(d[1]), "+f"(d[2]), "+f"(d[3])
        : "r"(a[0]), "r"(a[1]), "r"(a[2]), "r"(a[3]), "r"(b[0]), "r"(b[1]));
}
#define SWZC(row, c) ((unsigned)(((row)*4 + ((c) ^ (((row)>>1)&3)))*16))

// ------------------------- reduction helpers --------------------------------
__device__ __forceinline__ float blockReduceSum(float v, float* red) {
    for (int o = 16; o; o >>= 1) v += __shfl_down_sync(0xffffffffu, v, o);
    int w = threadIdx.x >> 5, l = threadIdx.x & 31;
    __syncthreads();
    if (l == 0) red[w] = v;
    __syncthreads();
    int nw = (blockDim.x + 31) >> 5;
    float r = (threadIdx.x < nw) ? red[threadIdx.x] : 0.0f;
    if (w == 0) {
        for (int o = 16; o; o >>= 1) r += __shfl_down_sync(0xffffffffu, r, o);
        if (l == 0) red[0] = r;
    }
    __syncthreads();
    return red[0];
}
__device__ __forceinline__ float blockReduceMax(float v, float* red) {
    for (int o = 16; o; o >>= 1) v = fmaxf(v, __shfl_down_sync(0xffffffffu, v, o));
    int w = threadIdx.x >> 5, l = threadIdx.x & 31;
    __syncthreads();
    if (l == 0) red[w] = v;
    __syncthreads();
    int nw = (blockDim.x + 31) >> 5;
    float r = (threadIdx.x < nw) ? red[threadIdx.x] : -3.4e38f;
    if (w == 0) {
        for (int o = 16; o; o >>= 1) r = fmaxf(r, __shfl_down_sync(0xffffffffu, r, o));
        if (l == 0) red[0] = r;
    }
    __syncthreads();
    return red[0];
}

// ------ W_eff builder (8 outputs/warp) + be tail + prep tail -----------------
__global__ void modw_kernel(const float* __restrict__ Wqm, const float* __restrict__ bqm,
                            const float* __restrict__ Wkm, const float* __restrict__ bkm,
                            const float* __restrict__ Wvm, const float* __restrict__ bvm,
                            const float* __restrict__ Wq, const float* __restrict__ Wk,
                            const float* __restrict__ Wv, const float* __restrict__ f,
                            const float* __restrict__ Wo, const float* __restrict__ bv,
                            const float* __restrict__ bo, const float* __restrict__ bq,
                            const float* __restrict__ bk,
                            const float* __restrict__ Wfo, const float* __restrict__ bfo,
                            const float* __restrict__ Wab, const float* __restrict__ bab,
                            const float* __restrict__ aemb) {
    int tid = threadIdx.x;
    int warp = tid >> 5, lane = tid & 31;

    if (blockIdx.x == MODW_BLOCKS + 96) {
        // ---- prep tail (single block, 256 threads) ----
        __shared__ float fs2[FPn];
        __shared__ float carr[Pp];
        __shared__ float red[32];
        __shared__ float p3s[2];
        if (tid < FPn) fs2[tid] = f[tid];
        for (int i = tid; i < 3*Dd; i += 256)
            g_bias[i] = (i < Dd) ? bq[i] : (i < 2*Dd) ? bk[i - Dd] : bv[i - 2*Dd];
        for (int i = tid; i < Bb*Dd; i += 256) g_pooled[i] = 0.0f;
        __syncthreads();
        if (tid < 2) {
            float s = bfo[tid];
            for (int c = 0; c < FPn; c++) s += Wfo[tid*FPn + c] * fs2[c];
            p3s[tid] = s;
        }
        if (tid >= 32 && tid < 32 + Ac) {
            int a = tid - 32;
            float s = bab[a];
            for (int c = 0; c < FPn; c++) s += Wab[a*FPn + c] * fs2[c];
            g_fpbias[a] = s;
        }
        __syncthreads();
        float scale = (1.0f / (1.0f + expf(-p3s[0]))) * 2.0f + 0.5f;
        float shift = tanhf(p3s[1]) * (float)Gg;
        for (int i = tid; i < Pp; i += 256) {
            int xg = i % Gg, yg = i / Gg;
            float cant = (float)(((xg + yg) * (xg + yg + 1)) / 2 + yg);
            carr[i] = cant * scale + shift;
        }
        __syncthreads();
        float mv = -3.4e38f;
        for (int i = tid; i < Pp; i += 256) mv = fmaxf(mv, carr[i]);
        float cmax = blockReduceMax(mv, red);
        float denom = fmaxf(cmax, 1.0f);
        for (int i = tid; i < Pp; i += 256) g_cnorm[i] = carr[i] / denom;
        for (int a = 0; a < Ac; a++) {
            float ss = 0.0f;
#pragma unroll
            for (int r = 0; r < 3; r++) {
                float xv = aemb[a*Dd + tid + r*256];
                ss += xv * xv;
            }
            ss = blockReduceSum(ss, red);
            float inv = 1.0f / fmaxf(sqrtf(ss), 1e-12f);
#pragma unroll
            for (int r = 0; r < 3; r++)
                g_anchors_n[a*Dd + tid + r*256] = aemb[a*Dd + tid + r*256] * inv;
            __syncthreads();
        }
        return;
    }

    if (blockIdx.x >= MODW_BLOCKS) {
        // ---- be tail: 96 blocks x 8 warps -> 768 outputs ----
        int e = (blockIdx.x - MODW_BLOCKS) * 8 + warp;
        const float* row = Wo + (long)e * Dd;
        float s = 0.0f;
        for (int j = lane; j < Dd; j += 32) s += row[j] * bv[j];
        for (int o = 16; o; o >>= 1) s += __shfl_down_sync(0xffffffffu, s, o);
        if (lane == 0) g_be[e] = s + bo[e];
        return;
    }

    __shared__ float fs[FPn];
    if (tid < FPn) fs[tid] = f[tid];
    __syncthreads();
    long base = ((long)blockIdx.x * 8 + warp) * 8;   // 8 consecutive outputs
    int s = (int)(base / ((long)Dd*Dd));
    int i0 = (int)(base % ((long)Dd*Dd));
    const float* Wm = (s == 0) ? Wqm : (s == 1) ? Wkm : Wvm;
    const float* bm = (s == 0) ? bqm : (s == 1) ? bkm : bvm;
    const float* Wb = (s == 0) ? Wq  : (s == 1) ? Wk  : Wv;
    float pp[8];
    float fa = fs[lane*2], fb = fs[lane*2 + 1];
#pragma unroll
    for (int r = 0; r < 8; r++) {
        float2 w2 = *(const float2*)(Wm + (long)(i0 + r) * FPn + lane * 2);
        pp[r] = w2.x * fa + w2.y * fb;
    }
    for (int o = 16; o; o >>= 1) {
#pragma unroll
        for (int r = 0; r < 8; r++)
            pp[r] += __shfl_down_sync(0xffffffffu, pp[r], o);
    }
    if (lane == 0) {
#pragma unroll
        for (int r = 0; r < 8; r++) {
            int i = i0 + r;
            int d = i / Dd, j = i % Dd;
            float w = Wb[(long)j*Dd + d] + 0.1f * (pp[r] + bm[i]);
            if (s < 2) g_Wcomb[(long)s * Dd * Dd + (long)j * Dd + d] = w;
            else       g_WvT[(long)d * Dd + j] = w;
        }
    }
}

// ------------------- FFMA2 SGEMM 128x128 (route-critical qk + Wc2) ----------
// MODE 1: A addressed as x patches, qk slicing (+bias)
// MODE 3: plain C = A*B^T, fp16 hi/lo split epilogue (Wc2 builder)
template<int MODE>
__global__ void __launch_bounds__(256, 2)
sgemm(const float* __restrict__ A, const float* __restrict__ Bt,
      const float* __restrict__ bias, float* __restrict__ C,
      int M, int N, int Kd) {
    const int tid = threadIdx.x;
    const int bm = blockIdx.y * 128;
    const int bn = blockIdx.x * 128;
    __shared__ float As[2][16][132];
    __shared__ float Bs[2][16][132];

    ull acc[8][4];
#pragma unroll
    for (int i = 0; i < 8; i++)
#pragma unroll
        for (int j = 0; j < 4; j++) acc[i][j] = pack2(0.0f, 0.0f);

    const int tx = tid & 15, ty = tid >> 4;
    const int lrow = tid >> 1;
    const int lcol = (tid & 1) * 4;

    int ar = bm + lrow; if (ar >= M) ar = M - 1;
    long aoff;
    if (MODE == 1) aoff = (long)(ar + ar / Pp + 1) * Kd;
    else           aoff = (long)ar * Kd;
    int br = bn + lrow; if (br >= N) br = N - 1;
    long boff = (long)br * Kd;

    // preload chunk 0 (k 0..15)
    {
        float4 av0 = *(const float4*)(A + aoff + lcol);
        float4 av1 = *(const float4*)(A + aoff + lcol + 8);
        float4 bv0 = *(const float4*)(Bt + boff + lcol);
        float4 bv1 = *(const float4*)(Bt + boff + lcol + 8);
        As[0][lcol+0][lrow] = av0.x; As[0][lcol+1][lrow] = av0.y;
        As[0][lcol+2][lrow] = av0.z; As[0][lcol+3][lrow] = av0.w;
        As[0][lcol+8][lrow] = av1.x; As[0][lcol+9][lrow] = av1.y;
        As[0][lcol+10][lrow] = av1.z; As[0][lcol+11][lrow] = av1.w;
        Bs[0][lcol+0][lrow] = bv0.x; Bs[0][lcol+1][lrow] = bv0.y;
        Bs[0][lcol+2][lrow] = bv0.z; Bs[0][lcol+3][lrow] = bv0.w;
        Bs[0][lcol+8][lrow] = bv1.x; Bs[0][lcol+9][lrow] = bv1.y;
        Bs[0][lcol+10][lrow] = bv1.z; Bs[0][lcol+11][lrow] = bv1.w;
    }
    __syncthreads();

    int cur = 0;
    for (int k0 = 16; k0 <= Kd; k0 += 16) {
        float4 av0, av1, bv0, bv1;
        if (k0 < Kd) {
            av0 = *(const float4*)(A + aoff + k0 + lcol);
            av1 = *(const float4*)(A + aoff + k0 + lcol + 8);
            bv0 = *(const float4*)(Bt + boff + k0 + lcol);
            bv1 = *(const float4*)(Bt + boff + k0 + lcol + 8);
        }
#pragma unroll
        for (int kk = 0; kk < 16; kk++) {
            float4 a0 = *(const float4*)&As[cur][kk][ty*4];
            float4 a1 = *(const float4*)&As[cur][kk][64 + ty*4];
            float4 b0 = *(const float4*)&Bs[cur][kk][tx*4];
            float4 b1 = *(const float4*)&Bs[cur][kk][64 + tx*4];
            ull bb0 = pack2(b0.x, b0.y);
            ull bb1 = pack2(b0.z, b0.w);
            ull bb2 = pack2(b1.x, b1.y);
            ull bb3 = pack2(b1.z, b1.w);
            float aa[8] = {a0.x, a0.y, a0.z, a0.w, a1.x, a1.y, a1.z, a1.w};
#pragma unroll
            for (int i = 0; i < 8; i++) {
                ull ap = pack2(aa[i], aa[i]);
                ffma2(acc[i][0], ap, bb0);
                ffma2(acc[i][1], ap, bb1);
                ffma2(acc[i][2], ap, bb2);
                ffma2(acc[i][3], ap, bb3);
            }
        }
        if (k0 < Kd) {
            int nxt = cur ^ 1;
            As[nxt][lcol+0][lrow] = av0.x; As[nxt][lcol+1][lrow] = av0.y;
            As[nxt][lcol+2][lrow] = av0.z; As[nxt][lcol+3][lrow] = av0.w;
            As[nxt][lcol+8][lrow] = av1.x; As[nxt][lcol+9][lrow] = av1.y;
            As[nxt][lcol+10][lrow] = av1.z; As[nxt][lcol+11][lrow] = av1.w;
            Bs[nxt][lcol+0][lrow] = bv0.x; Bs[nxt][lcol+1][lrow] = bv0.y;
            Bs[nxt][lcol+2][lrow] = bv0.z; Bs[nxt][lcol+3][lrow] = bv0.w;
            Bs[nxt][lcol+8][lrow] = bv1.x; Bs[nxt][lcol+9][lrow] = bv1.y;
            Bs[nxt][lcol+10][lrow] = bv1.z; Bs[nxt][lcol+11][lrow] = bv1.w;
        }
        __syncthreads();
        cur ^= 1;
    }

#pragma unroll
    for (int i = 0; i < 8; i++) {
        int gr = bm + ((i < 4) ? (ty*4 + i) : (64 + ty*4 + i - 4));
        if (gr >= M) continue;
#pragma unroll
        for (int j = 0; j < 4; j++) {
            int gc0 = bn + ((j < 2) ? (tx*4 + 2*j) : (64 + tx*4 + 2*(j - 2)));
            float2 vv = unpack2(acc[i][j]);
            float vals[2] = {vv.x, vv.y};
#pragma unroll
            for (int c = 0; c < 2; c++) {
                int gc = gc0 + c;
                if (gc >= N) continue;
                float v = vals[c];
                if (MODE == 3) {
                    __half h = __float2half_rn(v);
                    g_Wc2hi[(long)gr * N + gc] = h;
                    g_Wc2lo[(long)gr * N + gc] =
                        __float2half_rn((v - __half2float(h)) * LO_SCALE);
                } else {
                    int s = gc / Dd, c2 = gc % Dd;
                    C[(long)s * SLICE + (long)gr * Dd + c2] = v + bias[gc];
                }
            }
        }
    }
}

// ---------- FFMA2 scores GEMM: 144x96 tiles, zero padding, affinity epi -----
__global__ void __launch_bounds__(256, 2)
sgemm_sc(const float* __restrict__ A, const float* __restrict__ Bt,
         float* __restrict__ C, long sA, long sB, long sC) {
    const int tid = threadIdx.x;
    const int bm = blockIdx.y * 144;
    const int bn = blockIdx.x * 96;
    A  += (long)blockIdx.z * sA;
    Bt += (long)blockIdx.z * sB;
    C  += (long)blockIdx.z * sC;

    __shared__ float As[2][16][148];
    __shared__ float Bs[2][16][104];

    ull acc[9][3];
#pragma unroll
    for (int i = 0; i < 9; i++)
#pragma unroll
        for (int j = 0; j < 3; j++) acc[i][j] = pack2(0.0f, 0.0f);

    const int tx = tid & 15, ty = tid >> 4;

    float4 stg[4];
    auto ldg = [&](int k0) {
        int n = 0;
        for (int id = tid; id < 960; id += 256, n++) {
            int isB = (id >= 576);
            int id2 = isB ? id - 576 : id;
            int row = id2 >> 2, q = (id2 & 3) * 4;
            const float* src = isB ? (Bt + (long)(bn + row) * Dd + k0 + q)
                                   : (A  + (long)(bm + row) * Dd + k0 + q);
            stg[n] = *(const float4*)src;
        }
    };
    auto sts = [&](int buf) {
        int n = 0;
        for (int id = tid; id < 960; id += 256, n++) {
            int isB = (id >= 576);
            int id2 = isB ? id - 576 : id;
            int row = id2 >> 2, q = (id2 & 3) * 4;
            if (!isB) {
                As[buf][q+0][row] = stg[n].x; As[buf][q+1][row] = stg[n].y;
                As[buf][q+2][row] = stg[n].z; As[buf][q+3][row] = stg[n].w;
            } else {
                Bs[buf][q+0][row] = stg[n].x; Bs[buf][q+1][row] = stg[n].y;
                Bs[buf][q+2][row] = stg[n].z; Bs[buf][q+3][row] = stg[n].w;
            }
        }
    };

    ldg(0);
    sts(0);
    __syncthreads();

    int cur = 0;
    for (int k0 = 16; k0 <= Dd; k0 += 16) {
        if (k0 < Dd) ldg(k0);
#pragma unroll
        for (int kk = 0; kk < 16; kk++) {
            float a[9];
#pragma unroll
            for (int i = 0; i < 9; i++) a[i] = As[cur][kk][ty + 16*i];
            float2 b01 = *(const float2*)&Bs[cur][kk][tx*6];
            float2 b23 = *(const float2*)&Bs[cur][kk][tx*6 + 2];
            float2 b45 = *(const float2*)&Bs[cur][kk][tx*6 + 4];
            ull bb0 = pack2(b01.x, b01.y);
            ull bb1 = pack2(b23.x, b23.y);
            ull bb2 = pack2(b45.x, b45.y);
#pragma unroll
            for (int i = 0; i < 9; i++) {
                ull ap = pack2(a[i], a[i]);
                ffma2(acc[i][0], ap, bb0);
                ffma2(acc[i][1], ap, bb1);
                ffma2(acc[i][2], ap, bb2);
            }
        }
        if (k0 < Dd) sts(cur ^ 1);
        __syncthreads();
        cur ^= 1;
    }

#pragma unroll
    for (int i = 0; i < 9; i++) {
        int gr = bm + ty + 16*i;
        float cr = g_cnorm[gr];
#pragma unroll
        for (int jp = 0; jp < 3; jp++) {
            int gc = bn + tx*6 + 2*jp;
            float2 v = unpack2(acc[i][jp]);
            v.x += 0.3f * (1.0f - fabsf(cr - g_cnorm[gc]));
            v.y += 0.3f * (1.0f - fabsf(cr - g_cnorm[gc+1]));
            if (gr == gc)     v.x = NEGC;
            if (gr == gc + 1) v.y = NEGC;
            *(float2*)&C[(long)gr * Pp + gc] = v;
        }
    }
}

// ---- HMMA split-fp16 GEMM + FUSED final assembly ----------------------------
__global__ void __launch_bounds__(256, 2)
hmma_gemm(const __half* __restrict__ Ahi, const __half* __restrict__ Alo,
          const __half* __restrict__ Bhi, const __half* __restrict__ Blo,
          const float* __restrict__ bias, const float* __restrict__ x,
          const float* __restrict__ aw, float* __restrict__ out,
          int M, int N) {
    extern __shared__ char smem[];
    unsigned smb = smem_u32(smem);
    const int tid = threadIdx.x, lane = tid & 31, wid = tid >> 5;
    const int warp_m = wid & 3, warp_n = wid >> 2;      // 4 x 2 warp grid
    const int bm = blockIdx.y * 128, bn = blockIdx.x * 64;
    const int Mc = M - 1, Nc = N - 1;

    float accA[2][4][4], accB[2][4][4];
#pragma unroll
    for (int i = 0; i < 2; i++)
#pragma unroll
        for (int j = 0; j < 4; j++)
#pragma unroll
            for (int r = 0; r < 4; r++) { accA[i][j][r] = 0.0f; accB[i][j][r] = 0.0f; }

    auto load_stage = [&](int st, int k0) {
        unsigned sbase = smb + st * H_STG;
        for (int id = tid; id < 1536; id += 256) {
            const __half* src;
            unsigned dst;
            if (id < 1024) {
                int hl = id >> 9;
                int ida = id & 511;
                int row = ida >> 2, c = ida & 3;
                int gr = bm + row; if (gr > Mc) gr = Mc;
                src = (hl ? Alo : Ahi) + (long)gr * Dd + k0 + c * 8;
                dst = sbase + hl * 8192 + SWZC(row, c);
            } else {
                int id2 = id - 1024;
                int hl = (id2 >= 256) ? 1 : 0;
                int idb = id2 - hl * 256;
                int row = idb >> 2, c = idb & 3;
                int gr = bn + row; if (gr > Nc) gr = Nc;
                src = (hl ? Blo : Bhi) + (long)gr * Dd + k0 + c * 8;
                dst = sbase + 16384 + hl * 4096 + SWZC(row, c);
            }
            cp16(dst, src);
        }
    };

    load_stage(0, 0);
    cp_commit();

    for (int it = 0; it < NIT; ++it) {
        if (it + 1 < NIT) {
            load_stage((it + 1) & 1, (it + 1) * 32);
            cp_commit();
            cp_wait<1>();
        } else {
            cp_wait<0>();
        }
        __syncthreads();
        unsigned sA = smb + (it & 1) * H_STG;
#pragma unroll
        for (int k16 = 0; k16 < 2; ++k16) {
            unsigned a[2][2][4], b[2][2][4];
#pragma unroll
            for (int i = 0; i < 2; i++)
#pragma unroll
                for (int hl = 0; hl < 2; hl++) {
                    int row = warp_m * 32 + i * 16 + (lane & 15);
                    int c = k16 * 2 + (lane >> 4);
                    ldsm4(a[i][hl], sA + hl * 8192 + SWZC(row, c));
                }
#pragma unroll
            for (int j2 = 0; j2 < 2; j2++)
#pragma unroll
                for (int hl = 0; hl < 2; hl++) {
                    int row = warp_n * 32 + j2 * 16 + (lane & 7) + ((lane >> 4) << 3);
                    int c = k16 * 2 + ((lane >> 3) & 1);
                    ldsm4(b[j2][hl], sA + 16384 + hl * 4096 + SWZC(row, c));
                }
#pragma unroll
            for (int i = 0; i < 2; i++)
#pragma unroll
                for (int j = 0; j < 4; j++) {
                    int j2 = j >> 1, o = (j & 1) * 2;
                    mma16816(accA[i][j], a[i][0], &b[j2][0][o]);
                    mma16816(accB[i][j], a[i][0], &b[j2][1][o]);
                    mma16816(accB[i][j], a[i][1], &b[j2][0][o]);
                }
        }
        __syncthreads();
    }

    float sig = 1.0f / (1.0f + expf(-aw[0]));
#pragma unroll
    for (int i = 0; i < 2; i++)
#pragma unroll
        for (int j = 0; j < 4; j++)
#pragma unroll
            for (int h = 0; h < 2; h++) {
                int gr = bm + warp_m * 32 + i * 16 + h * 8 + (lane >> 2);
                int gc = bn + warp_n * 32 + j * 8 + (lane & 3) * 2;
                if (gr >= M) continue;
                int b = gr / Pp, p = gr - b * Pp;
                long oidx = ((long)b * (Pp + 1) + 1 + p) * (long)Dd + gc;
                float2 xv = *(const float2*)(x + oidx);
                float a0 = g_anchor_out[b * Dd + gc];
                float a1 = g_anchor_out[b * Dd + gc + 1];
                float v0 = accA[i][j][h*2]   + accB[i][j][h*2]   * LO_INV;
                float v1 = accA[i][j][h*2+1] + accB[i][j][h*2+1] * LO_INV;
                *(float2*)(out + oidx) = make_float2(
                    xv.x + (v0 + bias[gc])   + sig * a0,
                    xv.y + (v1 + bias[gc+1]) + sig * a1);
            }
}

// ------------------------- row L2 normalize (fp32, round-2 numerics) --------
__global__ void l2norm_kernel(float* __restrict__ qk) {
    long row = blockIdx.x;          // 0 .. 2*ROWS-1
    float* base = qk + row * (long)Dd;
    int tid = threadIdx.x;
    float v0 = base[tid], v1 = base[tid + 256], v2 = base[tid + 512];
    __shared__ float red[32];
    float ss = blockReduceSum(v0*v0 + v1*v1 + v2*v2, red);
    float inv = 1.0f / fmaxf(sqrtf(ss), 1e-12f);
    base[tid]       = v0 * inv;
    base[tid + 256] = v1 * inv;
    base[tid + 512] = v2 * inv;
}

// ---------- warp-per-row top-8 + softmax + weighted X gather (fp16 split) ----
__global__ void topk_kernel(const float* __restrict__ scores, const float* __restrict__ x,
                            float* __restrict__ out_routes, float* __restrict__ out_weights) {
    int warp = threadIdx.x >> 5, lane = threadIdx.x & 31;
    long row = (long)blockIdx.x * 8 + warp;
    if (row >= ROWS) return;
    int b = (int)(row / Pp);
    const float* srow = scores + row * Pp;

    float lv[18];
#pragma unroll
    for (int t = 0; t < 18; t++) lv[t] = srow[t*32 + lane];

    int ti[Kk]; float tv[Kk];
#pragma unroll
    for (int k = 0; k < Kk; k++) {
        float best = -3.4e38f; int bidx = 0x7fffffff;
#pragma unroll
        for (int t = 0; t < 18; t++) {
            float val = lv[t];
            if (val > best) { best = val; bidx = t*32 + lane; }
        }
        for (int o = 16; o; o >>= 1) {
            float ov = __shfl_xor_sync(0xffffffffu, best, o);
            int   oi = __shfl_xor_sync(0xffffffffu, bidx, o);
            if (ov > best || (ov == best && oi < bidx)) { best = ov; bidx = oi; }
        }
        tv[k] = best; ti[k] = bidx;
        if ((bidx & 31) == lane) lv[bidx >> 5] = -3.4e38f;
    }

    float mx = tv[0];
    float w[Kk]; float sum = 0.0f;
#pragma unroll
    for (int k = 0; k < Kk; k++) { w[k] = expf((tv[k] - mx) / TEMPc); sum += w[k]; }
    float inv = 1.0f / sum;
#pragma unroll
    for (int k = 0; k < Kk; k++) w[k] *= inv;

    if (lane < Kk) {
        float rr = 0.0f, ww = 0.0f;
#pragma unroll
        for (int k = 0; k < Kk; k++) if (lane == k) { rr = (float)ti[k]; ww = w[k]; }
        out_routes[row * Kk + lane]  = rr;
        out_weights[row * Kk + lane] = ww;
    }

    const float* xb = x + ((long)b * (Pp + 1) + 1) * Dd;
    long o = row * (long)Dd;
#pragma unroll 4
    for (int d = lane; d < Dd; d += 32) {
        float acc = 0.0f;
#pragma unroll
        for (int k = 0; k < Kk; k++)
            acc += w[k] * xb[(long)ti[k] * Dd + d];
        __half h = __float2half_rn(acc);
        g_Rhi[o + d] = h;
        g_Rlo[o + d] = __float2half_rn((acc - __half2float(h)) * LO_SCALE);
    }
}

// --------------- pooled = mean over patches (4-way split) + cls copy --------
__global__ void pooled_kernel(const float* __restrict__ x, float* __restrict__ out) {
    int b = blockIdx.x, seg = blockIdx.y, tid = threadIdx.x;
    float a0 = 0, a1 = 0, a2 = 0;
    const float* base = x + ((long)b * (Pp + 1) + 1 + seg * 144) * Dd;
    for (int p = 0; p < 144; p++) {
        const float* r = base + (long)p * Dd;
        a0 += r[tid]; a1 += r[tid + 256]; a2 += r[tid + 512];
    }
    const float inv = 1.0f / (float)Pp;
    atomicAdd(&g_pooled[b*Dd + tid],       a0 * inv);
    atomicAdd(&g_pooled[b*Dd + tid + 256], a1 * inv);
    atomicAdd(&g_pooled[b*Dd + tid + 512], a2 * inv);
    if (seg == 0) {
        long o = (long)b * (Pp + 1) * Dd;
#pragma unroll
        for (int r = 0; r < 3; r++) out[o + tid + r*256] = x[o + tid + r*256];
    }
}

// ------------- feat_proj + a_aff + wpool, zero anchor_out -------------------
__global__ void feat_kernel(const float* __restrict__ Wfp, const float* __restrict__ bfp) {
    int b = blockIdx.x, tid = threadIdx.x;
    __shared__ float ps[Dd];
    __shared__ float fps[Dd];
    __shared__ float red[32];
    __shared__ float logits[Ac];
    __shared__ float aff[Ac];
#pragma unroll
    for (int r = 0; r < 3; r++) ps[tid + r*256] = g_pooled[b*Dd + tid + r*256];
    __syncthreads();
#pragma unroll
    for (int r = 0; r < 3; r++) {
        int j = tid + r*256;
        float s = bfp[j];
        const float* w = Wfp + (long)j * Dd;
        for (int d = 0; d < Dd; d++) s += ps[d] * w[d];
        fps[j] = s;
    }
    __syncthreads();
    float ss = 0.0f;
#pragma unroll
    for (int r = 0; r < 3; r++) { float vv = fps[tid + r*256]; ss += vv * vv; }
    ss = blockReduceSum(ss, red);
    float inv = 1.0f / fmaxf(sqrtf(ss), 1e-12f);
#pragma unroll
    for (int r = 0; r < 3; r++) fps[tid + r*256] *= inv;
    __syncthreads();
    int w = tid >> 5, l = tid & 31;
    for (int a = w; a < Ac; a += 8) {
        float s = 0.0f;
        const float* an = g_anchors_n + a * Dd;
        for (int d = l; d < Dd; d += 32) s += fps[d] * an[d];
        for (int o = 16; o; o >>= 1) s += __shfl_down_sync(0xffffffffu, s, o);
        if (l == 0) logits[a] = s + 0.3f * g_fpbias[a];
    }
    __syncthreads();
    if (tid == 0) {
        float mx = logits[0];
        for (int a = 1; a < Ac; a++) mx = fmaxf(mx, logits[a]);
        float sum = 0.0f;
        for (int a = 0; a < Ac; a++) { float e = expf(logits[a] - mx); aff[a] = e; sum += e; }
        float is = 1.0f / sum;
        for (int a = 0; a < Ac; a++) aff[a] *= is;
    }
    __syncthreads();
    for (int idx = tid; idx < Ac * Dd; idx += 256)
        g_wpool[(long)b * Ac * Dd + idx] = aff[idx / Dd] * ps[idx % Dd];
#pragma unroll
    for (int r = 0; r < 3; r++) g_anchor_out[b*Dd + tid + r*256] = 0.0f;
}

// ---- anchor_out[b][e] += sum_{a,d} wpool[b][a*768+d] * aW[a][e][d] --------
__global__ void anchor_kernel(const float* __restrict__ aW) {
    int e0 = blockIdx.x * 64;
    int a0 = blockIdx.y * 2;
    int tid = threadIdx.x;
    __shared__ float Wt[64][33];
    __shared__ float wp[32][32];
    int e = tid & 63, bg = tid >> 6;
    float acc[8];
#pragma unroll
    for (int i = 0; i < 8; i++) acc[i] = 0.0f;
    int wr = tid >> 5, l = tid & 31;
    for (int a = a0; a < a0 + 2; a++) {
        for (int d0 = 0; d0 < Dd; d0 += 32) {
#pragma unroll
            for (int r = 0; r < 8; r++) {
                int ee = r * 8 + wr;
                Wt[ee][l] = aW[((long)a * Dd + e0 + ee) * Dd + d0 + l];
            }
            {
                int b_ = tid >> 3, dd = (tid & 7) * 4;
                float4 v4 = *(const float4*)(g_wpool + (long)b_ * Ac * Dd + a * Dd + d0 + dd);
                wp[b_][dd] = v4.x; wp[b_][dd+1] = v4.y; wp[b_][dd+2] = v4.z; wp[b_][dd+3] = v4.w;
            }
            __syncthreads();
#pragma unroll
            for (int dd = 0; dd < 32; dd++) {
                float wv = Wt[e][dd];
#pragma unroll
                for (int i = 0; i < 8; i++) acc[i] += wp[bg*8 + i][dd] * wv;
            }
            __syncthreads();
        }
    }
#pragma unroll
    for (int i = 0; i < 8; i++)
        atomicAdd(&g_anchor_out[(bg*8 + i) * Dd + e0 + e], acc[i]);
}

// ------------------------- launcher ----------------------------------------
extern "C" void kernel_launch(void* const* d_in, const int* in_sizes, int n_in,
                              void* d_out, int out_size) {
    const float* x    = (const float*)d_in[0];
    const float* f    = (const float*)d_in[1];
    const float* Wq   = (const float*)d_in[2];
    const float* bq   = (const float*)d_in[3];
    const float* Wk   = (const float*)d_in[4];
    const float* bk   = (const float*)d_in[5];
    const float* Wv   = (const float*)d_in[6];
    const float* bv   = (const float*)d_in[7];
    const float* Wo   = (const float*)d_in[8];
    const float* bo   = (const float*)d_in[9];
    const float* Wqm  = (const float*)d_in[10];
    const float* bqm  = (const float*)d_in[11];
    const float* Wkm  = (const float*)d_in[12];
    const float* bkm  = (const float*)d_in[13];
    const float* Wvm  = (const float*)d_in[14];
    const float* bvm  = (const float*)d_in[15];
    const float* Wfo  = (const float*)d_in[16];
    const float* bfo  = (const float*)d_in[17];
    const float* aemb = (const float*)d_in[18];
    const float* aW   = (const float*)d_in[19];
    const float* Wab  = (const float*)d_in[20];
    const float* bab  = (const float*)d_in[21];
    const float* Wfp  = (const float*)d_in[22];
    const float* bfp  = (const float*)d_in[23];
    const float* aw   = (const float*)d_in[24];

    float* out         = (float*)d_out;
    float* out_routes  = out;
    float* out_weights = out + (long)Bb * Pp * Kk;
    float* out_output  = out + 2L * Bb * Pp * Kk;

    float *p_Wc, *p_WvT, *p_qkv, *p_sc, *p_bias, *p_be;
    __half *p_Wc2hi, *p_Wc2lo, *p_Rhi, *p_Rlo;
    cudaGetSymbolAddress((void**)&p_Wc,    g_Wcomb);
    cudaGetSymbolAddress((void**)&p_WvT,   g_WvT);
    cudaGetSymbolAddress((void**)&p_qkv,   g_qkv);
    cudaGetSymbolAddress((void**)&p_sc,    g_scores);
    cudaGetSymbolAddress((void**)&p_bias,  g_bias);
    cudaGetSymbolAddress((void**)&p_be,    g_be);
    cudaGetSymbolAddress((void**)&p_Wc2hi, g_Wc2hi);
    cudaGetSymbolAddress((void**)&p_Wc2lo, g_Wc2lo);
    cudaGetSymbolAddress((void**)&p_Rhi,   g_Rhi);
    cudaGetSymbolAddress((void**)&p_Rlo,   g_Rlo);

    cudaFuncSetAttribute(hmma_gemm, cudaFuncAttributeMaxDynamicSharedMemorySize, H_SMEM);

    // 1: W_eff builder + be tail + prep tail (all independent prep work)
    modw_kernel<<<MODW_BLOCKS + 97, 256>>>(Wqm, bqm, Wkm, bkm, Wvm, bvm,
                                           Wq, Wk, Wv, f, Wo, bv, bo, bq, bk,
                                           Wfo, bfo, Wab, bab, aemb);

    // 2: q|k projection (route-critical): 128x128 tiles, round-2 numerics
    dim3 gQK(2 * Dd / 128, ROWS / 128);   // (12, 144)
    sgemm<1><<<gQK, 256>>>(x, p_Wc, p_bias, p_qkv, ROWS, 2 * Dd, Dd);

    // 3: row l2 normalize
    l2norm_kernel<<<2 * ROWS, 256>>>(p_qkv);

    // 4 (ncu): scores, 144x96 tiles
    sgemm_sc<<<dim3(Pp / 96, Pp / 144, Bb), 256>>>(
        p_qkv, p_qkv + SLICE, p_sc,
        (long)Pp * Dd, (long)Pp * Dd, (long)Pp * Pp);

    // 5: top-8 + softmax + gather
    topk_kernel<<<ROWS / 8, 256>>>(p_sc, x, out_routes, out_weights);

    // 6: pooled mean + cls copy
    pooled_kernel<<<dim3(Bb, 4), 256>>>(x, out_output);

    // 7: Wc2 = Wo @ Wv_eff, fp16 split epilogue
    sgemm<3><<<dim3(Dd / 128, Dd / 128), 256>>>(
        Wo, p_WvT, (const float*)0, (float*)0, Dd, Dd, Dd);

    feat_kernel<<<Bb, 256>>>(Wfp, bfp);                                              // 8
    anchor_kernel<<<dim3(Dd / 64, Ac / 2), 256>>>(aW);                               // 9

    // 10: fused out = x + (xr @ Wc2^T + be) + sig*anchor_out
    hmma_gemm<<<dim3(Dd / 64, ROWS / 128), 256, H_SMEM>>>(
        p_Rhi, p_Rlo, p_Wc2hi, p_Wc2lo, p_be, x, aw, out_output, ROWS, Dd);
}

// round 15
// speedup vs baseline: 1.0367x; 1.0367x over previous
#include <cuda_runtime.h>
#include <cuda_fp16.h>
#include <math.h>

#define Dd 768
#define Pp 576
#define Gg 24
#define Kk 8
#define FPn 64
#define Ac 16
#define Bb 32
#define NEGC -1000000000.0f
#define TEMPc 0.1f
#define ROWS (Bb*Pp)            /* 18432 */
#define SLICE ((long)ROWS*Dd)

#define NIT 24                  /* 768 / 32 */
#define H_STG 24576             /* A 16KB + B 8KB per stage */
#define H_SMEM (2*H_STG)

#define MODW_BLOCKS ((3*Dd*Dd)/64)   /* 27648 */

typedef unsigned long long ull;

// ------------------------- scratch (device globals) ------------------------
__device__ float g_Wcomb[2*Dd*Dd];      // fp32 combined weights: q | k
__device__ float g_WvT[Dd*Dd];          // Wv_eff transposed: [d][j]
__device__ float g_bias[3*Dd];
__device__ float g_be[Dd];              // Wo @ bv + bo
__device__ float g_qkv[2*ROWS*Dd];      // q | k (fp32)
__device__ float g_scores[Bb*Pp*Pp];
__device__ float g_cnorm[Pp];
__device__ float g_anchors_n[Ac*Dd];
__device__ float g_fpbias[Ac];
__device__ float g_pooled[Bb*Dd];
__device__ float g_wpool[Bb*Ac*Dd];
__device__ float g_anchor_out[Bb*Dd];

// fp16 split buffers (output-only path)
__device__ __half g_Wc2hi[Dd*Dd];       // (Wo @ Wv_eff) hi
__device__ __half g_Wc2lo[Dd*Dd];
__device__ __half g_Rhi[ROWS*Dd];       // gathered-x hi
__device__ __half g_Rlo[ROWS*Dd];

#define LO_SCALE 2048.0f
#define LO_INV   (1.0f/2048.0f)

// ------------------------- f32x2 helpers ------------------------------------
__device__ __forceinline__ void ffma2(ull &acc, ull a, ull b) {
    asm("fma.rn.f32x2 %0, %1, %2, %0;" : "+l"(acc) : "l"(a), "l"(b));
}
__device__ __forceinline__ ull pack2(float x, float y) {
    ull r;
    asm("mov.b64 %0, {%1, %2};" : "=l"(r) : "f"(x), "f"(y));
    return r;
}
__device__ __forceinline__ float2 unpack2(ull v) {
    float2 r;
    asm("mov.b64 {%0, %1}, %2;" : "=f"(r.x), "=f"(r.y) : "l"(v));
    return r;
}

// ------------------------- PTX helpers (HMMA path) ---------------------------
__device__ __forceinline__ unsigned smem_u32(const void* p) {
    unsigned a;
    asm("{ .reg .u64 t; cvta.to.shared.u64 t, %1; cvt.u32.u64 %0, t; }" : "=r"(a) : "l"(p));
    return a;
}
__device__ __forceinline__ void cp16(unsigned s, const void* g) {
    asm volatile("cp.async.ca.shared.global [%0], [%1], 16;" :: "r"(s), "l"(g) : "memory");
}
__device__ __forceinline__ void cp_commit() {
    asm volatile("cp.async.commit_group;" ::: "memory");
}
template<int N> __device__ __forceinline__ void cp_wait() {
    asm volatile("cp.async.wait_group %0;" :: "n"(N) : "memory");
}
__device__ __forceinline__ void ldsm4(unsigned* r, unsigned addr) {
    asm volatile("ldmatrix.sync.aligned.m8n8.x4.shared.b16 {%0,%1,%2,%3}, [%4];"
        : "=r"(r[0]), "=r"(r[1]), "=r"(r[2]), "=r"(r[3]) : "r"(addr));
}
__device__ __forceinline__ void mma16816(float* d, const unsigned* a, const unsigned* b) {
    asm volatile(
        "mma.sync.aligned.m16n8k16.row.col.f32.f16.f16.f32 "
        "{%0,%1,%2,%3}, {%4,%5,%6,%7}, {%8,%9}, {%0,%1,%2,%3};"
        : "+f"(d[0]), "+f"(d[1]), "+f"(d[2]), "+f"(d[3])
        : "r"(a[0]), "r"(a[1]), "r"(a[2]), "r"(a[3]), "r"(b[0]), "r"(b[1]));
}
#define SWZC(row, c) ((unsigned)(((row)*4 + ((c) ^ (((row)>>1)&3)))*16))

// ------------------------- reduction helpers --------------------------------
__device__ __forceinline__ float blockReduceSum(float v, float* red) {
    for (int o = 16; o; o >>= 1) v += __shfl_down_sync(0xffffffffu, v, o);
    int w = threadIdx.x >> 5, l = threadIdx.x & 31;
    __syncthreads();
    if (l == 0) red[w] = v;
    __syncthreads();
    int nw = (blockDim.x + 31) >> 5;
    float r = (threadIdx.x < nw) ? red[threadIdx.x] : 0.0f;
    if (w == 0) {
        for (int o = 16; o; o >>= 1) r += __shfl_down_sync(0xffffffffu, r, o);
        if (l == 0) red[0] = r;
    }
    __syncthreads();
    return red[0];
}
__device__ __forceinline__ float blockReduceMax(float v, float* red) {
    for (int o = 16; o; o >>= 1) v = fmaxf(v, __shfl_down_sync(0xffffffffu, v, o));
    int w = threadIdx.x >> 5, l = threadIdx.x & 31;
    __syncthreads();
    if (l == 0) red[w] = v;
    __syncthreads();
    int nw = (blockDim.x + 31) >> 5;
    float r = (threadIdx.x < nw) ? red[threadIdx.x] : -3.4e38f;
    if (w == 0) {
        for (int o = 16; o; o >>= 1) r = fmaxf(r, __shfl_down_sync(0xffffffffu, r, o));
        if (l == 0) red[0] = r;
    }
    __syncthreads();
    return red[0];
}

// ------ W_eff builder (8 outputs/warp) + be tail + prep tail -----------------
__global__ void modw_kernel(const float* __restrict__ Wqm, const float* __restrict__ bqm,
                            const float* __restrict__ Wkm, const float* __restrict__ bkm,
                            const float* __restrict__ Wvm, const float* __restrict__ bvm,
                            const float* __restrict__ Wq, const float* __restrict__ Wk,
                            const float* __restrict__ Wv, const float* __restrict__ f,
                            const float* __restrict__ Wo, const float* __restrict__ bv,
                            const float* __restrict__ bo, const float* __restrict__ bq,
                            const float* __restrict__ bk,
                            const float* __restrict__ Wfo, const float* __restrict__ bfo,
                            const float* __restrict__ Wab, const float* __restrict__ bab,
                            const float* __restrict__ aemb) {
    int tid = threadIdx.x;
    int warp = tid >> 5, lane = tid & 31;

    if (blockIdx.x == MODW_BLOCKS + 96) {
        // ---- prep tail (single block, 256 threads) ----
        __shared__ float fs2[FPn];
        __shared__ float carr[Pp];
        __shared__ float red[32];
        __shared__ float p3s[2];
        if (tid < FPn) fs2[tid] = f[tid];
        for (int i = tid; i < 3*Dd; i += 256)
            g_bias[i] = (i < Dd) ? bq[i] : (i < 2*Dd) ? bk[i - Dd] : bv[i - 2*Dd];
        for (int i = tid; i < Bb*Dd; i += 256) g_pooled[i] = 0.0f;
        __syncthreads();
        if (tid < 2) {
            float s = bfo[tid];
            for (int c = 0; c < FPn; c++) s += Wfo[tid*FPn + c] * fs2[c];
            p3s[tid] = s;
        }
        if (tid >= 32 && tid < 32 + Ac) {
            int a = tid - 32;
            float s = bab[a];
            for (int c = 0; c < FPn; c++) s += Wab[a*FPn + c] * fs2[c];
            g_fpbias[a] = s;
        }
        __syncthreads();
        float scale = (1.0f / (1.0f + expf(-p3s[0]))) * 2.0f + 0.5f;
        float shift = tanhf(p3s[1]) * (float)Gg;
        for (int i = tid; i < Pp; i += 256) {
            int xg = i % Gg, yg = i / Gg;
            float cant = (float)(((xg + yg) * (xg + yg + 1)) / 2 + yg);
            carr[i] = cant * scale + shift;
        }
        __syncthreads();
        float mv = -3.4e38f;
        for (int i = tid; i < Pp; i += 256) mv = fmaxf(mv, carr[i]);
        float cmax = blockReduceMax(mv, red);
        float denom = fmaxf(cmax, 1.0f);
        for (int i = tid; i < Pp; i += 256) g_cnorm[i] = carr[i] / denom;
        for (int a = 0; a < Ac; a++) {
            float ss = 0.0f;
#pragma unroll
            for (int r = 0; r < 3; r++) {
                float xv = aemb[a*Dd + tid + r*256];
                ss += xv * xv;
            }
            ss = blockReduceSum(ss, red);
            float inv = 1.0f / fmaxf(sqrtf(ss), 1e-12f);
#pragma unroll
            for (int r = 0; r < 3; r++)
                g_anchors_n[a*Dd + tid + r*256] = aemb[a*Dd + tid + r*256] * inv;
            __syncthreads();
        }
        return;
    }

    if (blockIdx.x >= MODW_BLOCKS) {
        // ---- be tail: 96 blocks x 8 warps -> 768 outputs ----
        int e = (blockIdx.x - MODW_BLOCKS) * 8 + warp;
        const float* row = Wo + (long)e * Dd;
        float s = 0.0f;
        for (int j = lane; j < Dd; j += 32) s += row[j] * bv[j];
        for (int o = 16; o; o >>= 1) s += __shfl_down_sync(0xffffffffu, s, o);
        if (lane == 0) g_be[e] = s + bo[e];
        return;
    }

    __shared__ float fs[FPn];
    if (tid < FPn) fs[tid] = f[tid];
    __syncthreads();
    long base = ((long)blockIdx.x * 8 + warp) * 8;   // 8 consecutive outputs
    int s = (int)(base / ((long)Dd*Dd));
    int i0 = (int)(base % ((long)Dd*Dd));
    const float* Wm = (s == 0) ? Wqm : (s == 1) ? Wkm : Wvm;
    const float* bm = (s == 0) ? bqm : (s == 1) ? bkm : bvm;
    const float* Wb = (s == 0) ? Wq  : (s == 1) ? Wk  : Wv;
    float pp[8];
    float fa = fs[lane*2], fb = fs[lane*2 + 1];
#pragma unroll
    for (int r = 0; r < 8; r++) {
        float2 w2 = *(const float2*)(Wm + (long)(i0 + r) * FPn + lane * 2);
        pp[r] = w2.x * fa + w2.y * fb;
    }
    for (int o = 16; o; o >>= 1) {
#pragma unroll
        for (int r = 0; r < 8; r++)
            pp[r] += __shfl_down_sync(0xffffffffu, pp[r], o);
    }
    if (lane == 0) {
#pragma unroll
        for (int r = 0; r < 8; r++) {
            int i = i0 + r;
            int d = i / Dd, j = i % Dd;
            float w = Wb[(long)j*Dd + d] + 0.1f * (pp[r] + bm[i]);
            if (s < 2) g_Wcomb[(long)s * Dd * Dd + (long)j * Dd + d] = w;
            else       g_WvT[(long)d * Dd + j] = w;
        }
    }
}

// ------------------- FFMA2 SGEMM 128x128 (route-critical qk + Wc2) ----------
// MODE 1: A addressed as x patches, qk slicing (+bias)
// MODE 3: plain C = A*B^T, fp16 hi/lo split epilogue (Wc2 builder)
template<int MODE>
__global__ void __launch_bounds__(256, 2)
sgemm(const float* __restrict__ A, const float* __restrict__ Bt,
      const float* __restrict__ bias, float* __restrict__ C,
      int M, int N, int Kd) {
    const int tid = threadIdx.x;
    const int bm = blockIdx.y * 128;
    const int bn = blockIdx.x * 128;
    __shared__ float As[2][16][132];
    __shared__ float Bs[2][16][132];

    ull acc[8][4];
#pragma unroll
    for (int i = 0; i < 8; i++)
#pragma unroll
        for (int j = 0; j < 4; j++) acc[i][j] = pack2(0.0f, 0.0f);

    const int tx = tid & 15, ty = tid >> 4;
    const int lrow = tid >> 1;
    const int lcol = (tid & 1) * 4;

    int ar = bm + lrow; if (ar >= M) ar = M - 1;
    long aoff;
    if (MODE == 1) aoff = (long)(ar + ar / Pp + 1) * Kd;
    else           aoff = (long)ar * Kd;
    int br = bn + lrow; if (br >= N) br = N - 1;
    long boff = (long)br * Kd;

    // preload chunk 0 (k 0..15)
    {
        float4 av0 = *(const float4*)(A + aoff + lcol);
        float4 av1 = *(const float4*)(A + aoff + lcol + 8);
        float4 bv0 = *(const float4*)(Bt + boff + lcol);
        float4 bv1 = *(const float4*)(Bt + boff + lcol + 8);
        As[0][lcol+0][lrow] = av0.x; As[0][lcol+1][lrow] = av0.y;
        As[0][lcol+2][lrow] = av0.z; As[0][lcol+3][lrow] = av0.w;
        As[0][lcol+8][lrow] = av1.x; As[0][lcol+9][lrow] = av1.y;
        As[0][lcol+10][lrow] = av1.z; As[0][lcol+11][lrow] = av1.w;
        Bs[0][lcol+0][lrow] = bv0.x; Bs[0][lcol+1][lrow] = bv0.y;
        Bs[0][lcol+2][lrow] = bv0.z; Bs[0][lcol+3][lrow] = bv0.w;
        Bs[0][lcol+8][lrow] = bv1.x; Bs[0][lcol+9][lrow] = bv1.y;
        Bs[0][lcol+10][lrow] = bv1.z; Bs[0][lcol+11][lrow] = bv1.w;
    }
    __syncthreads();

    int cur = 0;
    for (int k0 = 16; k0 <= Kd; k0 += 16) {
        float4 av0, av1, bv0, bv1;
        if (k0 < Kd) {
            av0 = *(const float4*)(A + aoff + k0 + lcol);
            av1 = *(const float4*)(A + aoff + k0 + lcol + 8);
            bv0 = *(const float4*)(Bt + boff + k0 + lcol);
            bv1 = *(const float4*)(Bt + boff + k0 + lcol + 8);
        }
#pragma unroll
        for (int kk = 0; kk < 16; kk++) {
            float4 a0 = *(const float4*)&As[cur][kk][ty*4];
            float4 a1 = *(const float4*)&As[cur][kk][64 + ty*4];
            float4 b0 = *(const float4*)&Bs[cur][kk][tx*4];
            float4 b1 = *(const float4*)&Bs[cur][kk][64 + tx*4];
            ull bb0 = pack2(b0.x, b0.y);
            ull bb1 = pack2(b0.z, b0.w);
            ull bb2 = pack2(b1.x, b1.y);
            ull bb3 = pack2(b1.z, b1.w);
            float aa[8] = {a0.x, a0.y, a0.z, a0.w, a1.x, a1.y, a1.z, a1.w};
#pragma unroll
            for (int i = 0; i < 8; i++) {
                ull ap = pack2(aa[i], aa[i]);
                ffma2(acc[i][0], ap, bb0);
                ffma2(acc[i][1], ap, bb1);
                ffma2(acc[i][2], ap, bb2);
                ffma2(acc[i][3], ap, bb3);
            }
        }
        if (k0 < Kd) {
            int nxt = cur ^ 1;
            As[nxt][lcol+0][lrow] = av0.x; As[nxt][lcol+1][lrow] = av0.y;
            As[nxt][lcol+2][lrow] = av0.z; As[nxt][lcol+3][lrow] = av0.w;
            As[nxt][lcol+8][lrow] = av1.x; As[nxt][lcol+9][lrow] = av1.y;
            As[nxt][lcol+10][lrow] = av1.z; As[nxt][lcol+11][lrow] = av1.w;
            Bs[nxt][lcol+0][lrow] = bv0.x; Bs[nxt][lcol+1][lrow] = bv0.y;
            Bs[nxt][lcol+2][lrow] = bv0.z; Bs[nxt][lcol+3][lrow] = bv0.w;
            Bs[nxt][lcol+8][lrow] = bv1.x; Bs[nxt][lcol+9][lrow] = bv1.y;
            Bs[nxt][lcol+10][lrow] = bv1.z; Bs[nxt][lcol+11][lrow] = bv1.w;
        }
        __syncthreads();
        cur ^= 1;
    }

#pragma unroll
    for (int i = 0; i < 8; i++) {
        int gr = bm + ((i < 4) ? (ty*4 + i) : (64 + ty*4 + i - 4));
        if (gr >= M) continue;
#pragma unroll
        for (int j = 0; j < 4; j++) {
            int gc0 = bn + ((j < 2) ? (tx*4 + 2*j) : (64 + tx*4 + 2*(j - 2)));
            float2 vv = unpack2(acc[i][j]);
            float vals[2] = {vv.x, vv.y};
#pragma unroll
            for (int c = 0; c < 2; c++) {
                int gc = gc0 + c;
                if (gc >= N) continue;
                float v = vals[c];
                if (MODE == 3) {
                    __half h = __float2half_rn(v);
                    g_Wc2hi[(long)gr * N + gc] = h;
                    g_Wc2lo[(long)gr * N + gc] =
                        __float2half_rn((v - __half2float(h)) * LO_SCALE);
                } else {
                    int s = gc / Dd, c2 = gc % Dd;
                    C[(long)s * SLICE + (long)gr * Dd + c2] = v + bias[gc];
                }
            }
        }
    }
}

// ---------- FFMA2 scores GEMM: 144x96 tiles, vectorized A fragments ---------
// Thread rows: {ty*4+i}, {64+ty*4+i}, {128+ty} -> float4/float4/scalar LDS.
// Per-output accumulation unchanged (k ascending, even/odd f32x2 pairing) ->
// bitwise identical scores.
__global__ void __launch_bounds__(256, 2)
sgemm_sc(const float* __restrict__ A, const float* __restrict__ Bt,
         float* __restrict__ C, long sA, long sB, long sC) {
    const int tid = threadIdx.x;
    const int bm = blockIdx.y * 144;
    const int bn = blockIdx.x * 96;
    A  += (long)blockIdx.z * sA;
    Bt += (long)blockIdx.z * sB;
    C  += (long)blockIdx.z * sC;

    __shared__ float As[2][16][148];
    __shared__ float Bs[2][16][104];

    ull acc[9][3];
#pragma unroll
    for (int i = 0; i < 9; i++)
#pragma unroll
        for (int j = 0; j < 3; j++) acc[i][j] = pack2(0.0f, 0.0f);

    const int tx = tid & 15, ty = tid >> 4;

    float4 stg[4];
    auto ldg = [&](int k0) {
        int n = 0;
        for (int id = tid; id < 960; id += 256, n++) {
            int isB = (id >= 576);
            int id2 = isB ? id - 576 : id;
            int row = id2 >> 2, q = (id2 & 3) * 4;
            const float* src = isB ? (Bt + (long)(bn + row) * Dd + k0 + q)
                                   : (A  + (long)(bm + row) * Dd + k0 + q);
            stg[n] = *(const float4*)src;
        }
    };
    auto sts = [&](int buf) {
        int n = 0;
        for (int id = tid; id < 960; id += 256, n++) {
            int isB = (id >= 576);
            int id2 = isB ? id - 576 : id;
            int row = id2 >> 2, q = (id2 & 3) * 4;
            if (!isB) {
                As[buf][q+0][row] = stg[n].x; As[buf][q+1][row] = stg[n].y;
                As[buf][q+2][row] = stg[n].z; As[buf][q+3][row] = stg[n].w;
            } else {
                Bs[buf][q+0][row] = stg[n].x; Bs[buf][q+1][row] = stg[n].y;
                Bs[buf][q+2][row] = stg[n].z; Bs[buf][q+3][row] = stg[n].w;
            }
        }
    };

    ldg(0);
    sts(0);
    __syncthreads();

    int cur = 0;
    for (int k0 = 16; k0 <= Dd; k0 += 16) {
        if (k0 < Dd) ldg(k0);
#pragma unroll
        for (int kk = 0; kk < 16; kk++) {
            float4 a0 = *(const float4*)&As[cur][kk][ty*4];
            float4 a1 = *(const float4*)&As[cur][kk][64 + ty*4];
            float a8v = As[cur][kk][128 + ty];
            float aa[9] = {a0.x, a0.y, a0.z, a0.w, a1.x, a1.y, a1.z, a1.w, a8v};
            float2 b01 = *(const float2*)&Bs[cur][kk][tx*6];
            float2 b23 = *(const float2*)&Bs[cur][kk][tx*6 + 2];
            float2 b45 = *(const float2*)&Bs[cur][kk][tx*6 + 4];
            ull bb0 = pack2(b01.x, b01.y);
            ull bb1 = pack2(b23.x, b23.y);
            ull bb2 = pack2(b45.x, b45.y);
#pragma unroll
            for (int i = 0; i < 9; i++) {
                ull ap = pack2(aa[i], aa[i]);
                ffma2(acc[i][0], ap, bb0);
                ffma2(acc[i][1], ap, bb1);
                ffma2(acc[i][2], ap, bb2);
            }
        }
        if (k0 < Dd) sts(cur ^ 1);
        __syncthreads();
        cur ^= 1;
    }

#pragma unroll
    for (int i = 0; i < 9; i++) {
        int gr = bm + ((i < 4) ? (ty*4 + i) : (i < 8) ? (64 + ty*4 + (i - 4)) : (128 + ty));
        float cr = g_cnorm[gr];
#pragma unroll
        for (int jp = 0; jp < 3; jp++) {
            int gc = bn + tx*6 + 2*jp;
            float2 v = unpack2(acc[i][jp]);
            v.x += 0.3f * (1.0f - fabsf(cr - g_cnorm[gc]));
            v.y += 0.3f * (1.0f - fabsf(cr - g_cnorm[gc+1]));
            if (gr == gc)     v.x = NEGC;
            if (gr == gc + 1) v.y = NEGC;
            *(float2*)&C[(long)gr * Pp + gc] = v;
        }
    }
}

// ---- HMMA split-fp16 GEMM + FUSED final assembly ----------------------------
__global__ void __launch_bounds__(256, 2)
hmma_gemm(const __half* __restrict__ Ahi, const __half* __restrict__ Alo,
          const __half* __restrict__ Bhi, const __half* __restrict__ Blo,
          const float* __restrict__ bias, const float* __restrict__ x,
          const float* __restrict__ aw, float* __restrict__ out,
          int M, int N) {
    extern __shared__ char smem[];
    unsigned smb = smem_u32(smem);
    const int tid = threadIdx.x, lane = tid & 31, wid = tid >> 5;
    const int warp_m = wid & 3, warp_n = wid >> 2;      // 4 x 2 warp grid
    const int bm = blockIdx.y * 128, bn = blockIdx.x * 64;
    const int Mc = M - 1, Nc = N - 1;

    float accA[2][4][4], accB[2][4][4];
#pragma unroll
    for (int i = 0; i < 2; i++)
#pragma unroll
        for (int j = 0; j < 4; j++)
#pragma unroll
            for (int r = 0; r < 4; r++) { accA[i][j][r] = 0.0f; accB[i][j][r] = 0.0f; }

    auto load_stage = [&](int st, int k0) {
        unsigned sbase = smb + st * H_STG;
        for (int id = tid; id < 1536; id += 256) {
            const __half* src;
            unsigned dst;
            if (id < 1024) {
                int hl = id >> 9;
                int ida = id & 511;
                int row = ida >> 2, c = ida & 3;
                int gr = bm + row; if (gr > Mc) gr = Mc;
                src = (hl ? Alo : Ahi) + (long)gr * Dd + k0 + c * 8;
                dst = sbase + hl * 8192 + SWZC(row, c);
            } else {
                int id2 = id - 1024;
                int hl = (id2 >= 256) ? 1 : 0;
                int idb = id2 - hl * 256;
                int row = idb >> 2, c = idb & 3;
                int gr = bn + row; if (gr > Nc) gr = Nc;
                src = (hl ? Blo : Bhi) + (long)gr * Dd + k0 + c * 8;
                dst = sbase + 16384 + hl * 4096 + SWZC(row, c);
            }
            cp16(dst, src);
        }
    };

    load_stage(0, 0);
    cp_commit();

    for (int it = 0; it < NIT; ++it) {
        if (it + 1 < NIT) {
            load_stage((it + 1) & 1, (it + 1) * 32);
            cp_commit();
            cp_wait<1>();
        } else {
            cp_wait<0>();
        }
        __syncthreads();
        unsigned sA = smb + (it & 1) * H_STG;
#pragma unroll
        for (int k16 = 0; k16 < 2; ++k16) {
            unsigned a[2][2][4], b[2][2][4];
#pragma unroll
            for (int i = 0; i < 2; i++)
#pragma unroll
                for (int hl = 0; hl < 2; hl++) {
                    int row = warp_m * 32 + i * 16 + (lane & 15);
                    int c = k16 * 2 + (lane >> 4);
                    ldsm4(a[i][hl], sA + hl * 8192 + SWZC(row, c));
                }
#pragma unroll
            for (int j2 = 0; j2 < 2; j2++)
#pragma unroll
                for (int hl = 0; hl < 2; hl++) {
                    int row = warp_n * 32 + j2 * 16 + (lane & 7) + ((lane >> 4) << 3);
                    int c = k16 * 2 + ((lane >> 3) & 1);
                    ldsm4(b[j2][hl], sA + 16384 + hl * 4096 + SWZC(row, c));
                }
#pragma unroll
            for (int i = 0; i < 2; i++)
#pragma unroll
                for (int j = 0; j < 4; j++) {
                    int j2 = j >> 1, o = (j & 1) * 2;
                    mma16816(accA[i][j], a[i][0], &b[j2][0][o]);
                    mma16816(accB[i][j], a[i][0], &b[j2][1][o]);
                    mma16816(accB[i][j], a[i][1], &b[j2][0][o]);
                }
        }
        __syncthreads();
    }

    float sig = 1.0f / (1.0f + expf(-aw[0]));
#pragma unroll
    for (int i = 0; i < 2; i++)
#pragma unroll
        for (int j = 0; j < 4; j++)
#pragma unroll
            for (int h = 0; h < 2; h++) {
                int gr = bm + warp_m * 32 + i * 16 + h * 8 + (lane >> 2);
                int gc = bn + warp_n * 32 + j * 8 + (lane & 3) * 2;
                if (gr >= M) continue;
                int b = gr / Pp, p = gr - b * Pp;
                long oidx = ((long)b * (Pp + 1) + 1 + p) * (long)Dd + gc;
                float2 xv = *(const float2*)(x + oidx);
                float a0 = g_anchor_out[b * Dd + gc];
                float a1 = g_anchor_out[b * Dd + gc + 1];
                float v0 = accA[i][j][h*2]   + accB[i][j][h*2]   * LO_INV;
                float v1 = accA[i][j][h*2+1] + accB[i][j][h*2+1] * LO_INV;
                *(float2*)(out + oidx) = make_float2(
                    xv.x + (v0 + bias[gc])   + sig * a0,
                    xv.y + (v1 + bias[gc+1]) + sig * a1);
            }
}

// ------------------------- row L2 normalize (fp32, round-2 numerics) --------
__global__ void l2norm_kernel(float* __restrict__ qk) {
    long row = blockIdx.x;          // 0 .. 2*ROWS-1
    float* base = qk + row * (long)Dd;
    int tid = threadIdx.x;
    float v0 = base[tid], v1 = base[tid + 256], v2 = base[tid + 512];
    __shared__ float red[32];
    float ss = blockReduceSum(v0*v0 + v1*v1 + v2*v2, red);
    float inv = 1.0f / fmaxf(sqrtf(ss), 1e-12f);
    base[tid]       = v0 * inv;
    base[tid + 256] = v1 * inv;
    base[tid + 512] = v2 * inv;
}

// ---------- warp-per-row top-8 + softmax + weighted X gather (fp16 split) ----
__global__ void topk_kernel(const float* __restrict__ scores, const float* __restrict__ x,
                            float* __restrict__ out_routes, float* __restrict__ out_weights) {
    int warp = threadIdx.x >> 5, lane = threadIdx.x & 31;
    long row = (long)blockIdx.x * 8 + warp;
    if (row >= ROWS) return;
    int b = (int)(row / Pp);
    const float* srow = scores + row * Pp;

    float lv[18];
#pragma unroll
    for (int t = 0; t < 18; t++) lv[t] = srow[t*32 + lane];

    int ti[Kk]; float tv[Kk];
#pragma unroll
    for (int k = 0; k < Kk; k++) {
        float best = -3.4e38f; int bidx = 0x7fffffff;
#pragma unroll
        for (int t = 0; t < 18; t++) {
            float val = lv[t];
            if (val > best) { best = val; bidx = t*32 + lane; }
        }
        for (int o = 16; o; o >>= 1) {
            float ov = __shfl_xor_sync(0xffffffffu, best, o);
            int   oi = __shfl_xor_sync(0xffffffffu, bidx, o);
            if (ov > best || (ov == best && oi < bidx)) { best = ov; bidx = oi; }
        }
        tv[k] = best; ti[k] = bidx;
        if ((bidx & 31) == lane) lv[bidx >> 5] = -3.4e38f;
    }

    float mx = tv[0];
    float w[Kk]; float sum = 0.0f;
#pragma unroll
    for (int k = 0; k < Kk; k++) { w[k] = expf((tv[k] - mx) / TEMPc); sum += w[k]; }
    float inv = 1.0f / sum;
#pragma unroll
    for (int k = 0; k < Kk; k++) w[k] *= inv;

    if (lane < Kk) {
        float rr = 0.0f, ww = 0.0f;
#pragma unroll
        for (int k = 0; k < Kk; k++) if (lane == k) { rr = (float)ti[k]; ww = w[k]; }
        out_routes[row * Kk + lane]  = rr;
        out_weights[row * Kk + lane] = ww;
    }

    const float* xb = x + ((long)b * (Pp + 1) + 1) * Dd;
    long o = row * (long)Dd;
#pragma unroll 4
    for (int d = lane; d < Dd; d += 32) {
        float acc = 0.0f;
#pragma unroll
        for (int k = 0; k < Kk; k++)
            acc += w[k] * xb[(long)ti[k] * Dd + d];
        __half h = __float2half_rn(acc);
        g_Rhi[o + d] = h;
        g_Rlo[o + d] = __float2half_rn((acc - __half2float(h)) * LO_SCALE);
    }
}

// --------------- pooled = mean over patches (4-way split) + cls copy --------
__global__ void pooled_kernel(const float* __restrict__ x, float* __restrict__ out) {
    int b = blockIdx.x, seg = blockIdx.y, tid = threadIdx.x;
    float a0 = 0, a1 = 0, a2 = 0;
    const float* base = x + ((long)b * (Pp + 1) + 1 + seg * 144) * Dd;
    for (int p = 0; p < 144; p++) {
        const float* r = base + (long)p * Dd;
        a0 += r[tid]; a1 += r[tid + 256]; a2 += r[tid + 512];
    }
    const float inv = 1.0f / (float)Pp;
    atomicAdd(&g_pooled[b*Dd + tid],       a0 * inv);
    atomicAdd(&g_pooled[b*Dd + tid + 256], a1 * inv);
    atomicAdd(&g_pooled[b*Dd + tid + 512], a2 * inv);
    if (seg == 0) {
        long o = (long)b * (Pp + 1) * Dd;
#pragma unroll
        for (int r = 0; r < 3; r++) out[o + tid + r*256] = x[o + tid + r*256];
    }
}

// ------------- feat_proj + a_aff + wpool, zero anchor_out -------------------
__global__ void feat_kernel(const float* __restrict__ Wfp, const float* __restrict__ bfp) {
    int b = blockIdx.x, tid = threadIdx.x;
    __shared__ float ps[Dd];
    __shared__ float fps[Dd];
    __shared__ float red[32];
    __shared__ float logits[Ac];
    __shared__ float aff[Ac];
#pragma unroll
    for (int r = 0; r < 3; r++) ps[tid + r*256] = g_pooled[b*Dd + tid + r*256];
    __syncthreads();
#pragma unroll
    for (int r = 0; r < 3; r++) {
        int j = tid + r*256;
        float s = bfp[j];
        const float* w = Wfp + (long)j * Dd;
        for (int d = 0; d < Dd; d++) s += ps[d] * w[d];
        fps[j] = s;
    }
    __syncthreads();
    float ss = 0.0f;
#pragma unroll
    for (int r = 0; r < 3; r++) { float vv = fps[tid + r*256]; ss += vv * vv; }
    ss = blockReduceSum(ss, red);
    float inv = 1.0f / fmaxf(sqrtf(ss), 1e-12f);
#pragma unroll
    for (int r = 0; r < 3; r++) fps[tid + r*256] *= inv;
    __syncthreads();
    int w = tid >> 5, l = tid & 31;
    for (int a = w; a < Ac; a += 8) {
        float s = 0.0f;
        const float* an = g_anchors_n + a * Dd;
        for (int d = l; d < Dd; d += 32) s += fps[d] * an[d];
        for (int o = 16; o; o >>= 1) s += __shfl_down_sync(0xffffffffu, s, o);
        if (l == 0) logits[a] = s + 0.3f * g_fpbias[a];
    }
    __syncthreads();
    if (tid == 0) {
        float mx = logits[0];
        for (int a = 1; a < Ac; a++) mx = fmaxf(mx, logits[a]);
        float sum = 0.0f;
        for (int a = 0; a < Ac; a++) { float e = expf(logits[a] - mx); aff[a] = e; sum += e; }
        float is = 1.0f / sum;
        for (int a = 0; a < Ac; a++) aff[a] *= is;
    }
    __syncthreads();
    for (int idx = tid; idx < Ac * Dd; idx += 256)
        g_wpool[(long)b * Ac * Dd + idx] = aff[idx / Dd] * ps[idx % Dd];
#pragma unroll
    for (int r = 0; r < 3; r++) g_anchor_out[b*Dd + tid + r*256] = 0.0f;
}

// ---- anchor_out[b][e] += sum_{a,d} wpool[b][a*768+d] * aW[a][e][d] --------
__global__ void anchor_kernel(const float* __restrict__ aW) {
    int e0 = blockIdx.x * 64;
    int a0 = blockIdx.y * 2;
    int tid = threadIdx.x;
    __shared__ float Wt[64][33];
    __shared__ float wp[32][32];
    int e = tid & 63, bg = tid >> 6;
    float acc[8];
#pragma unroll
    for (int i = 0; i < 8; i++) acc[i] = 0.0f;
    int wr = tid >> 5, l = tid & 31;
    for (int a = a0; a < a0 + 2; a++) {
        for (int d0 = 0; d0 < Dd; d0 += 32) {
#pragma unroll
            for (int r = 0; r < 8; r++) {
                int ee = r * 8 + wr;
                Wt[ee][l] = aW[((long)a * Dd + e0 + ee) * Dd + d0 + l];
            }
            {
                int b_ = tid >> 3, dd = (tid & 7) * 4;
                float4 v4 = *(const float4*)(g_wpool + (long)b_ * Ac * Dd + a * Dd + d0 + dd);
                wp[b_][dd] = v4.x; wp[b_][dd+1] = v4.y; wp[b_][dd+2] = v4.z; wp[b_][dd+3] = v4.w;
            }
            __syncthreads();
#pragma unroll
            for (int dd = 0; dd < 32; dd++) {
                float wv = Wt[e][dd];
#pragma unroll
                for (int i = 0; i < 8; i++) acc[i] += wp[bg*8 + i][dd] * wv;
            }
            __syncthreads();
        }
    }
#pragma unroll
    for (int i = 0; i < 8; i++)
        atomicAdd(&g_anchor_out[(bg*8 + i) * Dd + e0 + e], acc[i]);
}

// ------------------------- launcher ----------------------------------------
extern "C" void kernel_launch(void* const* d_in, const int* in_sizes, int n_in,
                              void* d_out, int out_size) {
    const float* x    = (const float*)d_in[0];
    const float* f    = (const float*)d_in[1];
    const float* Wq   = (const float*)d_in[2];
    const float* bq   = (const float*)d_in[3];
    const float* Wk   = (const float*)d_in[4];
    const float* bk   = (const float*)d_in[5];
    const float* Wv   = (const float*)d_in[6];
    const float* bv   = (const float*)d_in[7];
    const float* Wo   = (const float*)d_in[8];
    const float* bo   = (const float*)d_in[9];
    const float* Wqm  = (const float*)d_in[10];
    const float* bqm  = (const float*)d_in[11];
    const float* Wkm  = (const float*)d_in[12];
    const float* bkm  = (const float*)d_in[13];
    const float* Wvm  = (const float*)d_in[14];
    const float* bvm  = (const float*)d_in[15];
    const float* Wfo  = (const float*)d_in[16];
    const float* bfo  = (const float*)d_in[17];
    const float* aemb = (const float*)d_in[18];
    const float* aW   = (const float*)d_in[19];
    const float* Wab  = (const float*)d_in[20];
    const float* bab  = (const float*)d_in[21];
    const float* Wfp  = (const float*)d_in[22];
    const float* bfp  = (const float*)d_in[23];
    const float* aw   = (const float*)d_in[24];

    float* out         = (float*)d_out;
    float* out_routes  = out;
    float* out_weights = out + (long)Bb * Pp * Kk;
    float* out_output  = out + 2L * Bb * Pp * Kk;

    float *p_Wc, *p_WvT, *p_qkv, *p_sc, *p_bias, *p_be;
    __half *p_Wc2hi, *p_Wc2lo, *p_Rhi, *p_Rlo;
    cudaGetSymbolAddress((void**)&p_Wc,    g_Wcomb);
    cudaGetSymbolAddress((void**)&p_WvT,   g_WvT);
    cudaGetSymbolAddress((void**)&p_qkv,   g_qkv);
    cudaGetSymbolAddress((void**)&p_sc,    g_scores);
    cudaGetSymbolAddress((void**)&p_bias,  g_bias);
    cudaGetSymbolAddress((void**)&p_be,    g_be);
    cudaGetSymbolAddress((void**)&p_Wc2hi, g_Wc2hi);
    cudaGetSymbolAddress((void**)&p_Wc2lo, g_Wc2lo);
    cudaGetSymbolAddress((void**)&p_Rhi,   g_Rhi);
    cudaGetSymbolAddress((void**)&p_Rlo,   g_Rlo);

    cudaFuncSetAttribute(hmma_gemm, cudaFuncAttributeMaxDynamicSharedMemorySize, H_SMEM);

    // 1: W_eff builder + be tail + prep tail (all independent prep work)
    modw_kernel<<<MODW_BLOCKS + 97, 256>>>(Wqm, bqm, Wkm, bkm, Wvm, bvm,
                                           Wq, Wk, Wv, f, Wo, bv, bo, bq, bk,
                                           Wfo, bfo, Wab, bab, aemb);

    // 2: q|k projection (route-critical): 128x128 tiles, round-2 numerics
    dim3 gQK(2 * Dd / 128, ROWS / 128);   // (12, 144)
    sgemm<1><<<gQK, 256>>>(x, p_Wc, p_bias, p_qkv, ROWS, 2 * Dd, Dd);

    // 3: row l2 normalize
    l2norm_kernel<<<2 * ROWS, 256>>>(p_qkv);

    // 4 (ncu): scores, 144x96 tiles, vectorized A fragments
    sgemm_sc<<<dim3(Pp / 96, Pp / 144, Bb), 256>>>(
        p_qkv, p_qkv + SLICE, p_sc,
        (long)Pp * Dd, (long)Pp * Dd, (long)Pp * Pp);

    // 5: top-8 + softmax + gather
    topk_kernel<<<ROWS / 8, 256>>>(p_sc, x, out_routes, out_weights);

    // 6: pooled mean + cls copy
    pooled_kernel<<<dim3(Bb, 4), 256>>>(x, out_output);

    // 7: Wc2 = Wo @ Wv_eff, fp16 split epilogue
    sgemm<3><<<dim3(Dd / 128, Dd / 128), 256>>>(
        Wo, p_WvT, (const float*)0, (float*)0, Dd, Dd, Dd);

    feat_kernel<<<Bb, 256>>>(Wfp, bfp);                                              // 8
    anchor_kernel<<<dim3(Dd / 64, Ac / 2), 256>>>(aW);                               // 9

    // 10: fused out = x + (xr @ Wc2^T + be) + sig*anchor_out
    hmma_gemm<<<dim3(Dd / 64, ROWS / 128), 256, H_SMEM>>>(
        p_Rhi, p_Rlo, p_Wc2hi, p_Wc2lo, p_be, x, aw, out_output, ROWS, Dd);
}